// round 4
// baseline (speedup 1.0000x reference)
#include <cuda_runtime.h>

#define B_      2
#define CIN     64
#define HIN     128
#define WIN     256
#define COUT    64
#define KK      9
#define HOUT    128
#define WOUT    256
#define HW      (HIN * WIN)     // 32768
#define HWO     (HOUT * WOUT)   // 32768
#define PT      32              // pixels per stage-2 block

// Scratch (no allocation allowed): transposed weights + intermediate Y
__device__ float g_wT[KK * CIN * COUT];
__device__ float g_Y[(size_t)B_ * KK * HW * COUT];   // Y[b][k][pos][o], ~151 MB

__global__ void transpose_weight_kernel(const float* __restrict__ w) {
    int idx = blockIdx.x * blockDim.x + threadIdx.x;
    if (idx < COUT * CIN * KK) {
        int k = idx % KK;
        int c = (idx / KK) % CIN;
        int o = idx / (KK * CIN);
        g_wT[(k * CIN + c) * COUT + o] = w[idx];
    }
}

// ---- packed fp32x2 helpers ----
__device__ __forceinline__ void fma2(unsigned long long& d,
                                     unsigned long long a,
                                     unsigned long long b) {
    asm("fma.rn.f32x2 %0, %1, %2, %0;" : "+l"(d) : "l"(a), "l"(b));
}

// ============================================================================
// Stage 1: Y[b][k][pos][o] = sum_c x[b][c][pos] * W[o][c][k]   (dense GEMM)
// Block: 64 positions x 64 outputs x 9 k. 128 threads.
// ============================================================================
__global__ __launch_bounds__(128) void stage1_kernel(const float* __restrict__ x)
{
    __shared__ __align__(16) float2 s_x2[CIN][64];   // x duplicated (v,v)  32 KB
    __shared__ __align__(16) float  s_w[CIN][COUT];  // W_k [c][o]          16 KB

    const int tid  = threadIdx.x;
    const int b    = blockIdx.y;
    const int pos0 = blockIdx.x * 64;

    // load x tile [c][pos0..pos0+64), duplicated for f32x2
    {
        const int c   = tid >> 1;
        const int seg = tid & 1;
        const float* src = x + ((size_t)b * CIN + c) * HW + pos0 + seg * 32;
#pragma unroll
        for (int j = 0; j < 8; j++) {
            float4 v = *reinterpret_cast<const float4*>(src + j * 4);
            float4* d = reinterpret_cast<float4*>(&s_x2[c][seg * 32 + j * 4]);
            d[0] = make_float4(v.x, v.x, v.y, v.y);
            d[1] = make_float4(v.z, v.z, v.w, v.w);
        }
    }

    const int og = tid & 7;    // outputs [og*8, og*8+8)
    const int pg = tid >> 3;   // positions [pg*4, pg*4+4)

    for (int k = 0; k < KK; k++) {
        __syncthreads();   // x-tile ready (k=0) / previous GEMM done reading s_w
        // stage W_k -> smem
        {
            const float4* src = reinterpret_cast<const float4*>(g_wT + k * CIN * COUT);
            float4* dst = reinterpret_cast<float4*>(&s_w[0][0]);
#pragma unroll
            for (int i = 0; i < 8; i++)
                dst[i * 128 + tid] = src[i * 128 + tid];
        }
        __syncthreads();

        unsigned long long acc2[4][4];
#pragma unroll
        for (int j = 0; j < 4; j++)
#pragma unroll
            for (int p = 0; p < 4; p++) acc2[j][p] = 0ULL;

#pragma unroll 4
        for (int c = 0; c < CIN; c++) {
            const ulonglong2 sp01 = *reinterpret_cast<const ulonglong2*>(&s_x2[c][pg << 2]);
            const ulonglong2 sp23 = *reinterpret_cast<const ulonglong2*>(&s_x2[c][(pg << 2) + 2]);
            const ulonglong2 wp01 = *reinterpret_cast<const ulonglong2*>(&s_w[c][og << 3]);
            const ulonglong2 wp23 = *reinterpret_cast<const ulonglong2*>(&s_w[c][(og << 3) + 4]);

            fma2(acc2[0][0], wp01.x, sp01.x); fma2(acc2[0][1], wp01.x, sp01.y);
            fma2(acc2[0][2], wp01.x, sp23.x); fma2(acc2[0][3], wp01.x, sp23.y);
            fma2(acc2[1][0], wp01.y, sp01.x); fma2(acc2[1][1], wp01.y, sp01.y);
            fma2(acc2[1][2], wp01.y, sp23.x); fma2(acc2[1][3], wp01.y, sp23.y);
            fma2(acc2[2][0], wp23.x, sp01.x); fma2(acc2[2][1], wp23.x, sp01.y);
            fma2(acc2[2][2], wp23.x, sp23.x); fma2(acc2[2][3], wp23.x, sp23.y);
            fma2(acc2[3][0], wp23.y, sp01.x); fma2(acc2[3][1], wp23.y, sp01.y);
            fma2(acc2[3][2], wp23.y, sp23.x); fma2(acc2[3][3], wp23.y, sp23.y);
        }

        // store Y[b][k][pos][o] (o-pairs contiguous)
        float* yk = g_Y + ((size_t)(b * KK + k) * HW + pos0 + (pg << 2)) * COUT + (og << 3);
#pragma unroll
        for (int p = 0; p < 4; p++) {
            unsigned long long* row = reinterpret_cast<unsigned long long*>(yk + (size_t)p * COUT);
            row[0] = acc2[0][p];
            row[1] = acc2[1][p];
            row[2] = acc2[2][p];
            row[3] = acc2[3][p];
        }
    }
}

// ============================================================================
// Stage 2: out[b][o][p] = bias[o] + sum_k bilinear(Y[b][k][.][o]; offset)
// Block: PT=32 pixels, 128 threads = 4 warps x 8 pixels each.
// Warp layout per (pixel,k): lanes 0-15 read row pos (o-chunks), lanes 16-31
// read row pos+1; x-corners fused into one contiguous 512B load.
// ============================================================================
__global__ __launch_bounds__(128) void stage2_kernel(const float* __restrict__ offset,
                                                     const float* __restrict__ bias,
                                                     float* __restrict__ out)
{
    __shared__ float s_out[PT][COUT + 4];

    const int tid  = threadIdx.x;
    const int warp = tid >> 5;
    const int lane = tid & 31;
    const int gp0  = blockIdx.x * PT;        // global pixel id (b*HWO + p), block-uniform b
    const int half = lane >> 4;              // 0: row y, 1: row y (x+1 slot)
    const int oq   = lane & 15;              // o-chunk = oq*4

    const int gpw   = gp0 + warp * 8;
    const int b     = gpw >> 15;             // HWO = 32768
    const int pbase = gpw & (HWO - 1);

    for (int i = 0; i < 8; i++) {
        const int p = pbase + i;
        const int h = p >> 8;
        const int w = p & 255;
        float4 acc = make_float4(0.f, 0.f, 0.f, 0.f);

#pragma unroll
        for (int k = 0; k < KK; k++) {
            const int ki = k / 3, kj = k - 3 * ki;
            const float offy = __ldg(offset + ((size_t)(b * KK + k) * 2 + 0) * HWO + p);
            const float offx = __ldg(offset + ((size_t)(b * KK + k) * 2 + 1) * HWO + p);
            const float py = (float)(h - 1 + ki) + offy;
            const float px = (float)(w - 1 + kj) + offx;
            const float y0f = floorf(py), x0f = floorf(px);
            const float wy = py - y0f, wx = px - x0f;
            const int y0 = (int)y0f, x0 = (int)x0f;
            const int y1 = y0 + 1, x1 = x0 + 1;
            const bool vy0 = (y0 >= 0) & (y0 < HIN);
            const bool vy1 = (y1 >= 0) & (y1 < HIN);
            const bool vx0 = (x0 >= 0) & (x0 < WIN);
            const bool vx1 = (x1 >= 0) & (x1 < WIN);

            float w00 = (1.f - wy) * (1.f - wx);
            float w01 = (1.f - wy) * wx;
            float w10 = wy * (1.f - wx);
            float w11 = wy * wx;
            if (!(vy0 && vx0)) w00 = 0.f;
            if (!(vy0 && vx1)) w01 = 0.f;
            if (!(vy1 && vx0)) w10 = 0.f;
            if (!(vy1 && vx1)) w11 = 0.f;

            // fused row-pair load at x0c, x0c+1; slot-select coefficients:
            //   x0 in [0,WIN-2]: slot0 <- x0 (w00/w10), slot1 <- x1 (w01/w11)
            //   x0 <  0       : slot0 <- x1 (w01/w11), slot1 unused
            //   x0 >  WIN-2   : slot0 unused,          slot1 <- x0 (w00/w10)
            const int x0c = min(max(x0, 0), WIN - 2);
            const int y0c = min(max(y0, 0), HIN - 1);
            const int y1c = min(max(y1, 0), HIN - 1);
            const bool lo_edge = (x0 < 0);
            const bool hi_edge = (x0 > WIN - 2);
            const float cA0 = lo_edge ? w01 : (hi_edge ? 0.f : w00);
            const float cA1 = lo_edge ? 0.f : (hi_edge ? w00 : w01);
            const float cB0 = lo_edge ? w11 : (hi_edge ? 0.f : w10);
            const float cB1 = lo_edge ? 0.f : (hi_edge ? w10 : w11);

            const float ca = half ? cA1 : cA0;
            const float cb = half ? cB1 : cB0;

            const size_t slab = (size_t)(b * KK + k) * HW;
            const float4 va = *reinterpret_cast<const float4*>(
                g_Y + (slab + (size_t)y0c * WIN + x0c) * COUT + lane * 4);
            const float4 vb = *reinterpret_cast<const float4*>(
                g_Y + (slab + (size_t)y1c * WIN + x0c) * COUT + lane * 4);

            acc.x += ca * va.x + cb * vb.x;
            acc.y += ca * va.y + cb * vb.y;
            acc.z += ca * va.z + cb * vb.z;
            acc.w += ca * va.w + cb * vb.w;
        }

        // combine the two halves (slot0 + slot1) and stash to smem
        float4 hi;
        hi.x = __shfl_down_sync(0xffffffffu, acc.x, 16);
        hi.y = __shfl_down_sync(0xffffffffu, acc.y, 16);
        hi.z = __shfl_down_sync(0xffffffffu, acc.z, 16);
        hi.w = __shfl_down_sync(0xffffffffu, acc.w, 16);
        if (half == 0) {
            float4 r = make_float4(acc.x + hi.x, acc.y + hi.y,
                                   acc.z + hi.z, acc.w + hi.w);
            *reinterpret_cast<float4*>(&s_out[warp * 8 + i][oq * 4]) = r;
        }
    }

    __syncthreads();

    // coalesced epilogue: out[b][o][p0..p0+32)
    const int o    = tid & 63;
    const int part = tid >> 6;               // 0/1 -> 16-pixel halves
    const int b2   = gp0 >> 15;
    const int p0   = gp0 & (HWO - 1);
    const float bv = __ldg(bias + o);
    float* dst = out + ((size_t)b2 * COUT + o) * HWO + p0 + part * 16;
#pragma unroll
    for (int j = 0; j < 4; j++) {
        const int pp = part * 16 + j * 4;
        float4 r = make_float4(s_out[pp + 0][o] + bv, s_out[pp + 1][o] + bv,
                               s_out[pp + 2][o] + bv, s_out[pp + 3][o] + bv);
        *reinterpret_cast<float4*>(dst + j * 4) = r;
    }
}

extern "C" void kernel_launch(void* const* d_in, const int* in_sizes, int n_in,
                              void* d_out, int out_size)
{
    const float* x      = (const float*)d_in[0];
    const float* offset = (const float*)d_in[1];
    const float* weight = (const float*)d_in[2];
    const float* bias   = (const float*)d_in[3];
    float* out          = (float*)d_out;

    transpose_weight_kernel<<<(COUT * CIN * KK + 255) / 256, 256>>>(weight);

    dim3 g1(HW / 64, B_);
    stage1_kernel<<<g1, 128>>>(x);

    stage2_kernel<<<(B_ * HWO) / PT, 128>>>(offset, bias, out);
}

// round 8
// speedup vs baseline: 1.3697x; 1.3697x over previous
#include <cuda_runtime.h>

#define B_      2
#define CIN     64
#define HIN     128
#define WIN     256
#define COUT    64
#define KK      9
#define HOUT    128
#define WOUT    256
#define HW      (HIN * WIN)     // 32768
#define HWO     (HOUT * WOUT)   // 32768
#define NTHREADS 128
#define SROW    68              // s_smp row stride in floats (16B-aligned, swizzle-friendly)

// Scratch (no allocation allowed)
__device__ float g_wT[KK * CIN * COUT];                 // wT[k][c][o]
__device__ float g_xT[(size_t)B_ * HW * CIN];           // xT[b][pos][c]  16.8 MB (L2-resident)

__global__ void transpose_weight_kernel(const float* __restrict__ w) {
    int idx = blockIdx.x * blockDim.x + threadIdx.x;
    if (idx < COUT * CIN * KK) {
        int k = idx % KK;
        int c = (idx / KK) % CIN;
        int o = idx / (KK * CIN);
        g_wT[(k * CIN + c) * COUT + o] = w[idx];
    }
}

// xT[b][pos][c] = x[b][c][pos]; tiles of 64 ch x 32 pos, both phases coalesced
__global__ __launch_bounds__(256) void transpose_x_kernel(const float* __restrict__ x) {
    __shared__ float t[CIN][33];
    const int tid  = threadIdx.x;
    const int pos0 = blockIdx.x * 32;
    const int b    = blockIdx.y;

    {
        const int pl = tid & 31;       // pos lane
        const int c0 = tid >> 5;       // 8 c per iter
#pragma unroll
        for (int i = 0; i < 8; i++) {
            const int c = c0 + i * 8;
            t[c][pl] = x[((size_t)b * CIN + c) * HW + pos0 + pl];
        }
    }
    __syncthreads();
    {
        const int c  = tid & 63;
        const int p0 = tid >> 6;       // 4 pos per iter
#pragma unroll
        for (int i = 0; i < 8; i++) {
            const int p = p0 + i * 4;
            g_xT[((size_t)b * HW + pos0 + p) * CIN + c] = t[c][p];
        }
    }
}

// ---- packed fp32x2 helpers ----
__device__ __forceinline__ unsigned long long pack2(float a, float b) {
    unsigned long long r;
    asm("mov.b64 %0, {%1, %2};" : "=l"(r) : "f"(a), "f"(b));
    return r;
}
__device__ __forceinline__ void fma2(unsigned long long& d,
                                     unsigned long long a,
                                     unsigned long long b) {
    asm("fma.rn.f32x2 %0, %1, %2, %0;" : "+l"(d) : "l"(a), "l"(b));
}
__device__ __forceinline__ void unpack2(unsigned long long v, float& a, float& b) {
    asm("mov.b64 {%0, %1}, %2;" : "=f"(a), "=f"(b) : "l"(v));
}

__global__ __launch_bounds__(NTHREADS) void deform_conv_kernel(
    const float* __restrict__ offset,
    const float* __restrict__ bias,
    float* __restrict__ out)
{
    // samples, plain scalar, XOR-swizzled in 4-pixel groups: element (c,p) lives at
    // word c*SROW + 4*((p>>2) ^ ((c>>2)&7)) + (p&3)
    __shared__ __align__(16) float s_smp[CIN][SROW];   // 17.4 KB
    __shared__ __align__(16) float s_w[CIN][COUT];     // 16 KB

    const int tid    = threadIdx.x;
    const int wtile  = blockIdx.x;   // 0..3
    const int h      = blockIdx.y;   // 0..127
    const int b      = blockIdx.z;   // 0..1
    const int w_base = wtile * 64;

    // sampling role: half-warp <-> one pixel; lane covers 4 contiguous channels
    const int warp = tid >> 5;
    const int lane = tid & 31;
    const int half = lane >> 4;       // pixel-within-pair
    const int cl   = lane & 15;       // channels 4*cl .. 4*cl+3

    // GEMM role: 8 outputs x 4 pixels per thread
    const int og = tid & 7;
    const int pg = tid >> 3;

    const float* xTb = g_xT + (size_t)b * HW * CIN;

    unsigned long long acc2[4][4];
#pragma unroll
    for (int j = 0; j < 4; j++)
#pragma unroll
        for (int p = 0; p < 4; p++) acc2[j][p] = 0ULL;

    for (int k = 0; k < KK; k++) {
        __syncthreads();   // previous GEMM done reading smem

        // stage weights wT[k] -> s_w (coalesced float4)
        {
            const float4* src = reinterpret_cast<const float4*>(g_wT + k * CIN * COUT);
            float4* dst = reinterpret_cast<float4*>(&s_w[0][0]);
#pragma unroll
            for (int i = 0; i < 8; i++)
                dst[i * NTHREADS + tid] = src[i * NTHREADS + tid];
        }

        // sampling: channel-contiguous corner gathers from xT
        const int ki = k / 3, kj = k - 3 * ki;
#pragma unroll
        for (int it = 0; it < 8; it++) {
            const int p     = it * 8 + warp * 2 + half;   // 0..63, each exactly once
            const int w_out = w_base + p;

            const float offy = __ldg(offset + ((size_t)(b * KK + k) * 2 + 0) * HWO + h * WOUT + w_out);
            const float offx = __ldg(offset + ((size_t)(b * KK + k) * 2 + 1) * HWO + h * WOUT + w_out);
            const float py = (float)(h - 1 + ki) + offy;
            const float px = (float)(w_out - 1 + kj) + offx;
            const float y0f = floorf(py), x0f = floorf(px);
            const float wy = py - y0f, wx = px - x0f;
            const int y0 = (int)y0f, x0 = (int)x0f;
            const int y1 = y0 + 1, x1 = x0 + 1;
            const bool vy0 = (y0 >= 0) & (y0 < HIN);
            const bool vy1 = (y1 >= 0) & (y1 < HIN);
            const bool vx0 = (x0 >= 0) & (x0 < WIN);
            const bool vx1 = (x1 >= 0) & (x1 < WIN);

            float w00 = (1.f - wy) * (1.f - wx);
            float w01 = (1.f - wy) * wx;
            float w10 = wy * (1.f - wx);
            float w11 = wy * wx;
            if (!(vy0 && vx0)) w00 = 0.f;
            if (!(vy0 && vx1)) w01 = 0.f;
            if (!(vy1 && vx0)) w10 = 0.f;
            if (!(vy1 && vx1)) w11 = 0.f;

            const int y0c = min(max(y0, 0), HIN - 1);
            const int y1c = min(max(y1, 0), HIN - 1);
            const int x0c = min(max(x0, 0), WIN - 1);
            const int x1c = min(max(x1, 0), WIN - 1);

            const int cofs = cl * 4;
            const float4 v00 = *reinterpret_cast<const float4*>(xTb + ((size_t)(y0c * WIN + x0c)) * CIN + cofs);
            const float4 v01 = *reinterpret_cast<const float4*>(xTb + ((size_t)(y0c * WIN + x1c)) * CIN + cofs);
            const float4 v10 = *reinterpret_cast<const float4*>(xTb + ((size_t)(y1c * WIN + x0c)) * CIN + cofs);
            const float4 v11 = *reinterpret_cast<const float4*>(xTb + ((size_t)(y1c * WIN + x1c)) * CIN + cofs);

            float4 r;
            r.x = w00 * v00.x + w01 * v01.x + w10 * v10.x + w11 * v11.x;
            r.y = w00 * v00.y + w01 * v01.y + w10 * v10.y + w11 * v11.y;
            r.z = w00 * v00.z + w01 * v01.z + w10 * v10.z + w11 * v11.z;
            r.w = w00 * v00.w + w01 * v01.w + w10 * v10.w + w11 * v11.w;

            // swizzled transposed store: channels 4*cl+j at pixel p
            const int wofs = ((p >> 2) ^ (cl & 7)) * 4 + (p & 3);
            s_smp[cofs + 0][wofs] = r.x;
            s_smp[cofs + 1][wofs] = r.y;
            s_smp[cofs + 2][wofs] = r.z;
            s_smp[cofs + 3][wofs] = r.w;
        }

        __syncthreads();

        // GEMM: acc[o][p] += W[k][c][o] * s[c][p]  (packed f32x2 over o-pairs)
#pragma unroll 32
        for (int c = 0; c < CIN; c++) {
            const int sw = (c >> 2) & 7;                       // const-folded (unrolled)
            const float4 sv = *reinterpret_cast<const float4*>(&s_smp[c][(pg ^ sw) << 2]);
            const ulonglong2 wp01 = *reinterpret_cast<const ulonglong2*>(&s_w[c][og << 3]);
            const ulonglong2 wp23 = *reinterpret_cast<const ulonglong2*>(&s_w[c][(og << 3) + 4]);

            const unsigned long long s0 = pack2(sv.x, sv.x);
            const unsigned long long s1 = pack2(sv.y, sv.y);
            const unsigned long long s2 = pack2(sv.z, sv.z);
            const unsigned long long s3 = pack2(sv.w, sv.w);

            fma2(acc2[0][0], wp01.x, s0); fma2(acc2[0][1], wp01.x, s1);
            fma2(acc2[0][2], wp01.x, s2); fma2(acc2[0][3], wp01.x, s3);
            fma2(acc2[1][0], wp01.y, s0); fma2(acc2[1][1], wp01.y, s1);
            fma2(acc2[1][2], wp01.y, s2); fma2(acc2[1][3], wp01.y, s3);
            fma2(acc2[2][0], wp23.x, s0); fma2(acc2[2][1], wp23.x, s1);
            fma2(acc2[2][2], wp23.x, s2); fma2(acc2[2][3], wp23.x, s3);
            fma2(acc2[3][0], wp23.y, s0); fma2(acc2[3][1], wp23.y, s1);
            fma2(acc2[3][2], wp23.y, s2); fma2(acc2[3][3], wp23.y, s3);
        }
    }

    // epilogue: unpack, add bias, float4 stores
    float vals[8][4];
#pragma unroll
    for (int j = 0; j < 4; j++)
#pragma unroll
        for (int p = 0; p < 4; p++)
            unpack2(acc2[j][p], vals[2 * j][p], vals[2 * j + 1][p]);

#pragma unroll
    for (int i = 0; i < 8; i++) {
        const int o = (og << 3) + i;
        const float bv = __ldg(bias + o);
        float4 r = make_float4(vals[i][0] + bv, vals[i][1] + bv,
                               vals[i][2] + bv, vals[i][3] + bv);
        *reinterpret_cast<float4*>(
            out + (((size_t)b * COUT + o) * HOUT + h) * WOUT + w_base + (pg << 2)) = r;
    }
}

extern "C" void kernel_launch(void* const* d_in, const int* in_sizes, int n_in,
                              void* d_out, int out_size)
{
    const float* x      = (const float*)d_in[0];
    const float* offset = (const float*)d_in[1];
    const float* weight = (const float*)d_in[2];
    const float* bias   = (const float*)d_in[3];
    float* out          = (float*)d_out;

    transpose_weight_kernel<<<(COUT * CIN * KK + 255) / 256, 256>>>(weight);

    dim3 gx(HW / 32, B_);
    transpose_x_kernel<<<gx, 256>>>(x);

    dim3 grid(WOUT / 64, HOUT, B_);
    deform_conv_kernel<<<grid, NTHREADS>>>(offset, bias, out);
}